// round 16
// baseline (speedup 1.0000x reference)
#include <cuda_runtime.h>
#include <cuda_fp16.h>
#include <cstdint>
#include <cstddef>

// Problem constants
#define BATCH   2
#define TSEQ    2048
#define DMODEL  1024
#define NHEADS  16
#define DKEY    64
#define DFF     4096
#define NTOK    (BATCH*TSEQ)          // 4096
#define QKVROW  (3*NHEADS*DKEY)       // 3072

// ---------------- scratch ----------------------------------------------------
__device__ float g_x1  [(size_t)NTOK*DMODEL];

// single fp16 activations
__device__ __half g_xn  [(size_t)NTOK*DMODEL];
__device__ __half g_xn2 [(size_t)NTOK*DMODEL];
__device__ __half g_ctx [(size_t)NTOK*DMODEL];
__device__ __half g_h   [(size_t)NTOK*DFF];

// qkv output: [tok][3072] (Q scaled by log2(e)/8 in cols 0..1023)
__device__ __half g_qsp [(size_t)NTOK*QKVROW];

// single-fp16 transposed weights [N, K] K-major
__device__ __half g_wqkvf[(size_t)QKVROW*DMODEL];
__device__ __half g_wof  [(size_t)DMODEL*DMODEL];
__device__ __half g_w1f  [(size_t)DFF*DMODEL];
__device__ __half g_w2f  [(size_t)DMODEL*DFF];

// ---------------- helpers ----------------------------------------------------
__device__ __forceinline__ uint32_t smem_u32(const void* p) {
    uint32_t a;
    asm("{ .reg .u64 t; cvta.to.shared.u64 t, %1; cvt.u32.u64 %0, t; }"
        : "=r"(a) : "l"(p));
    return a;
}
#define CP_ASYNC16(dst, src) \
    asm volatile("cp.async.cg.shared.global [%0], [%1], 16;" :: "r"(dst), "l"(src) : "memory")
#define CP_COMMIT() asm volatile("cp.async.commit_group;" ::: "memory")
#define CP_WAIT0()  asm volatile("cp.async.wait_group 0;"  ::: "memory")
#define CP_WAIT1()  asm volatile("cp.async.wait_group 1;"  ::: "memory")
#define CP_WAIT2()  asm volatile("cp.async.wait_group 2;"  ::: "memory")

__device__ __forceinline__ void ldmat4(uint32_t (&r)[4], uint32_t addr) {
    asm volatile("ldmatrix.sync.aligned.m8n8.x4.shared.b16 {%0,%1,%2,%3}, [%4];"
        : "=r"(r[0]), "=r"(r[1]), "=r"(r[2]), "=r"(r[3]) : "r"(addr));
}
__device__ __forceinline__ void ldmat4t(uint32_t (&r)[4], uint32_t addr) {
    asm volatile("ldmatrix.sync.aligned.m8n8.x4.trans.shared.b16 {%0,%1,%2,%3}, [%4];"
        : "=r"(r[0]), "=r"(r[1]), "=r"(r[2]), "=r"(r[3]) : "r"(addr));
}
__device__ __forceinline__ void mma16816h(float (&d)[4], const uint32_t (&a)[4],
                                          const uint32_t b0, const uint32_t b1) {
    asm volatile("mma.sync.aligned.m16n8k16.row.col.f32.f16.f16.f32 "
        "{%0,%1,%2,%3}, {%4,%5,%6,%7}, {%8,%9}, {%0,%1,%2,%3};"
        : "+f"(d[0]), "+f"(d[1]), "+f"(d[2]), "+f"(d[3])
        : "r"(a[0]), "r"(a[1]), "r"(a[2]), "r"(a[3]), "r"(b0), "r"(b1));
}
__device__ __forceinline__ uint32_t h2u(__half2 v) {
    union { __half2 h; uint32_t u; } c; c.h = v; return c.u;
}
// packed fp16x2 exp2 on the MUFU pipe (1 issue slot per 2 values)
__device__ __forceinline__ uint32_t ex2_h2(uint32_t x) {
    uint32_t r;
    asm("ex2.approx.f16x2 %0, %1;" : "=r"(r) : "r"(x));
    return r;
}

// ---------------- LayerNorm -> single fp16 -----------------------------------
__inline__ __device__ float warp_sum(float v) {
    #pragma unroll
    for (int o = 16; o > 0; o >>= 1) v += __shfl_xor_sync(0xffffffffu, v, o);
    return v;
}

__global__ __launch_bounds__(256) void ln_f16(
    const float* __restrict__ x, const float* __restrict__ g,
    const float* __restrict__ b, __half* __restrict__ y)
{
    const int row = blockIdx.x;
    const int tid = threadIdx.x;
    const float* xr = x + (size_t)row * DMODEL;

    float4 v = reinterpret_cast<const float4*>(xr)[tid];
    float s  = v.x + v.y + v.z + v.w;
    float sq = v.x*v.x + v.y*v.y + v.z*v.z + v.w*v.w;

    __shared__ float sh_s[8], sh_q[8];
    float ws = warp_sum(s), wq = warp_sum(sq);
    int warp = tid >> 5, lane = tid & 31;
    if (lane == 0) { sh_s[warp] = ws; sh_q[warp] = wq; }
    __syncthreads();
    __shared__ float sh_mean, sh_rstd;
    if (tid == 0) {
        float ts = 0.f, tq = 0.f;
        #pragma unroll
        for (int i = 0; i < 8; i++) { ts += sh_s[i]; tq += sh_q[i]; }
        float mean = ts * (1.0f / DMODEL);
        float var  = tq * (1.0f / DMODEL) - mean * mean;
        sh_mean = mean; sh_rstd = rsqrtf(var + 1e-5f);
    }
    __syncthreads();
    float mean = sh_mean, rstd = sh_rstd;

    float4 gv = reinterpret_cast<const float4*>(g)[tid];
    float4 bv = reinterpret_cast<const float4*>(b)[tid];
    float ox = (v.x - mean) * rstd * gv.x + bv.x;
    float oy = (v.y - mean) * rstd * gv.y + bv.y;
    float oz = (v.z - mean) * rstd * gv.z + bv.z;
    float ow = (v.w - mean) * rstd * gv.w + bv.w;

    size_t o = (size_t)row * DMODEL + tid * 4;
    *reinterpret_cast<__half2*>(y + o)     = __floats2half2_rn(ox, oy);
    *reinterpret_cast<__half2*>(y + o + 2) = __floats2half2_rn(oz, ow);
}

// ---------------- fused weight transpose: all 4 weights in one launch --------
__global__ __launch_bounds__(256) void wconv_all(
    const float* __restrict__ Wqkv, const float* __restrict__ Wo,
    const float* __restrict__ W1,   const float* __restrict__ W2,
    __half* __restrict__ oqkv, __half* __restrict__ oo,
    __half* __restrict__ o1,   __half* __restrict__ o2)
{
    __shared__ float t[32][33];
    const int bid = blockIdx.x;
    const float* W; __half* out; int K, N, n0, k0;
    if (bid < 3072)      { W = Wqkv; out = oqkv; K = 1024; N = 3072;
                           n0 = (bid % 96) * 32;  k0 = (bid / 96) * 32; }
    else if (bid < 4096) { int b2 = bid - 3072; W = Wo; out = oo; K = 1024; N = 1024;
                           n0 = (b2 % 32) * 32;  k0 = (b2 / 32) * 32; }
    else if (bid < 8192) { int b2 = bid - 4096; W = W1; out = o1; K = 1024; N = 4096;
                           n0 = (b2 % 128) * 32; k0 = (b2 / 128) * 32; }
    else                 { int b2 = bid - 8192; W = W2; out = o2; K = 4096; N = 1024;
                           n0 = (b2 % 32) * 32;  k0 = (b2 / 32) * 32; }

    const int tx = threadIdx.x & 31, ty = threadIdx.x >> 5;
    #pragma unroll
    for (int j = 0; j < 4; j++)
        t[ty + j*8][tx] = W[(size_t)(k0 + ty + j*8) * N + n0 + tx];
    __syncthreads();
    #pragma unroll
    for (int j = 0; j < 4; j++) {
        int n = ty + j*8;
        out[(size_t)(n0 + n) * K + k0 + tx] = __float2half_rn(t[tx][n]);
    }
}

// ---------------- 1-product fp16 GEMM, CTA 256x128, warp 64x64, 4-stage ------
#define GPITCH 144u
#define GT_A   (256u * GPITCH)     // 36864
#define GT_B   (128u * GPITCH)     // 18432
#define G1STG  (GT_A + GT_B)       // 55296
#define G1SMEM (4u * G1STG)        // 221184

template<bool RELU, bool RES, bool OF16, bool QKSCALE>
__global__ __launch_bounds__(256, 1) void gemm_f16(
    const __half* __restrict__ Af, const __half* __restrict__ Bf,
    const float* __restrict__ bias, const float* __restrict__ res,
    float* __restrict__ C, __half* __restrict__ Ch, int N, int K)
{
    extern __shared__ char sm[];
    const int tid = threadIdx.x, wid = tid >> 5, lane = tid & 31;
    const int m0 = blockIdx.y * 256, n0 = blockIdx.x * 128;
    const uint32_t sb = smem_u32(sm);

    const int mw = (wid & 3) * 64;
    const int nw = (wid >> 2) * 64;
    const int lg = lane >> 3, lr = lane & 7;

    float d[4][8][4];
    #pragma unroll
    for (int mt = 0; mt < 4; mt++)
        #pragma unroll
        for (int nt = 0; nt < 8; nt++)
            #pragma unroll
            for (int i = 0; i < 4; i++) d[mt][nt][i] = 0.f;

    const int nkt = K >> 6;

    auto loadStage = [&](int s, int k0) {
        const uint32_t st = sb + (uint32_t)s * G1STG;
        const __half* baseA = Af + (size_t)m0 * K + k0;
        const __half* baseB = Bf + (size_t)n0 * K + k0;
        #pragma unroll
        for (int i = 0; i < 8; i++) {
            int lin = i * 256 + tid;
            int row = lin >> 3, seg = lin & 7;
            uint32_t off = (uint32_t)row * GPITCH + (uint32_t)seg * 16u;
            CP_ASYNC16(st + off, (const char*)(baseA + (size_t)row * K + seg * 8));
        }
        #pragma unroll
        for (int i = 0; i < 4; i++) {
            int lin = i * 256 + tid;
            int row = lin >> 3, seg = lin & 7;
            uint32_t off = (uint32_t)row * GPITCH + (uint32_t)seg * 16u;
            CP_ASYNC16(st + GT_A + off, (const char*)(baseB + (size_t)row * K + seg * 8));
        }
        CP_COMMIT();
    };

    auto mmaStage = [&](int s) {
        const uint32_t AS = sb + (uint32_t)s * G1STG;
        const uint32_t BS = AS + GT_A;
        #pragma unroll
        for (int kh = 0; kh < 4; kh++) {
            uint32_t af[4][4];
            #pragma unroll
            for (int mt = 0; mt < 4; mt++) {
                uint32_t roff = (uint32_t)(mw + mt*16 + lr + ((lg & 1) << 3)) * GPITCH
                              + (uint32_t)(kh*16 + ((lg >> 1) << 3)) * 2u;
                ldmat4(af[mt], AS + roff);
            }
            #pragma unroll
            for (int bt = 0; bt < 4; bt++) {
                uint32_t roff = (uint32_t)(nw + bt*16 + lr + ((lg & 2) ? 8 : 0)) * GPITCH
                              + (uint32_t)(kh*16 + ((lg & 1) << 3)) * 2u;
                uint32_t bh[4];
                ldmat4(bh, BS + roff);
                #pragma unroll
                for (int mt = 0; mt < 4; mt++) {
                    mma16816h(d[mt][2*bt+0], af[mt], bh[0], bh[1]);
                    mma16816h(d[mt][2*bt+1], af[mt], bh[2], bh[3]);
                }
            }
        }
    };

    loadStage(0, 0);
    loadStage(1, 64);
    loadStage(2, 128);
    for (int kt = 0; kt < nkt; kt++) {
        if (kt + 2 < nkt)      { CP_WAIT2(); }
        else if (kt + 1 < nkt) { CP_WAIT1(); }
        else                   { CP_WAIT0(); }
        __syncthreads();
        if (kt + 3 < nkt) loadStage((kt + 3) & 3, (kt + 3) << 6);
        mmaStage(kt & 3);
    }

    const int qr = lane >> 2;
    const int qc = (lane & 3) * 2;
    #pragma unroll
    for (int mt = 0; mt < 4; mt++) {
        const int r0 = m0 + mw + mt * 16 + qr;
        const int r1 = r0 + 8;
        #pragma unroll
        for (int nt = 0; nt < 8; nt++) {
            const int c = n0 + nw + nt * 8 + qc;
            float2 bb = *reinterpret_cast<const float2*>(bias + c);
            float2 o0, o1;
            o0.x = d[mt][nt][0] + bb.x; o0.y = d[mt][nt][1] + bb.y;
            o1.x = d[mt][nt][2] + bb.x; o1.y = d[mt][nt][3] + bb.y;
            if (QKSCALE) {
                // Q columns: 1/8 (dk scale) x log2(e)  -> scores in log2 domain
                const float sc = (c < 1024) ? 0.18033688011112042f : 1.0f;
                o0.x *= sc; o0.y *= sc; o1.x *= sc; o1.y *= sc;
            }
            if (RELU) {
                o0.x = fmaxf(o0.x, 0.f); o0.y = fmaxf(o0.y, 0.f);
                o1.x = fmaxf(o1.x, 0.f); o1.y = fmaxf(o1.y, 0.f);
            }
            if (RES) {
                float2 u0 = *reinterpret_cast<const float2*>(res + (size_t)r0 * N + c);
                float2 u1 = *reinterpret_cast<const float2*>(res + (size_t)r1 * N + c);
                o0.x += u0.x; o0.y += u0.y; o1.x += u1.x; o1.y += u1.y;
            }
            if (OF16) {
                *reinterpret_cast<__half2*>(Ch + (size_t)r0 * N + c) = __floats2half2_rn(o0.x, o0.y);
                *reinterpret_cast<__half2*>(Ch + (size_t)r1 * N + c) = __floats2half2_rn(o1.x, o1.y);
            } else {
                *reinterpret_cast<float2*>(C + (size_t)r0 * N + c) = o0;
                *reinterpret_cast<float2*>(C + (size_t)r1 * N + c) = o1;
            }
        }
    }
}

// ---------------- MMA flash attention: BK=128 stages, 1 sync per stage -------
// Max-free log2-domain softmax; row sums via ones-MMA on the tensor pipe.
#define APITCH 144u
#define AQ_B   (128u * APITCH)             // 18432
#define AKV2_B (128u * APITCH)             // per K or V tile (128 keys)
#define ASTG2  (2u * AKV2_B)               // K+V stage = 36864
#define ASMEM  (AQ_B + 2u * ASTG2)         // 92160  (2 CTAs/SM: 184KB)
#define ONESH2 0x3C003C00u                 // half2(1,1)

__global__ __launch_bounds__(256, 2) void flash_mma(
    const __half* __restrict__ qsp, __half* __restrict__ ctx)
{
    extern __shared__ char sm[];
    const int tid = threadIdx.x, wid = tid >> 5, lane = tid & 31;
    const int q0 = (15 - blockIdx.x) * 128;
    const int bh = blockIdx.y, b = bh >> 4, h = bh & 15;
    const int mw = wid * 16;
    const int lg = lane >> 3, lr = lane & 7;
    const int qr = lane >> 2, qc = (lane & 3) * 2;

    const uint32_t sb = smem_u32(sm);
    const uint32_t QS = sb;
    const uint32_t ST = sb + AQ_B;

    {
        const __half* qb = qsp + (size_t)(b*TSEQ + q0) * QKVROW + h*64;
        #pragma unroll
        for (int i = 0; i < 4; i++) {
            int lin = i * 256 + tid;
            int row = lin >> 3, seg = lin & 7;
            uint32_t off = (uint32_t)row * APITCH + (uint32_t)seg * 16u;
            CP_ASYNC16(QS + off, (const char*)(qb + (size_t)row * QKVROW) + seg * 16);
        }
        CP_COMMIT();
    }

    // load 128 keys of K and V (V natural [t][d], transposed in-LDSM at use)
    auto loadKV = [&](int s, int key0) {
        const uint32_t Ks = ST + (uint32_t)s * ASTG2;
        const uint32_t Vs = Ks + AKV2_B;
        const __half* kb = qsp + (size_t)(b*TSEQ + key0) * QKVROW + 1024 + h*64;
        const __half* vb = qsp + (size_t)(b*TSEQ + key0) * QKVROW + 2048 + h*64;
        #pragma unroll
        for (int i = 0; i < 4; i++) {
            int lin = i * 256 + tid;
            int row = lin >> 3, seg = lin & 7;
            uint32_t off = (uint32_t)row * APITCH + (uint32_t)seg * 16u;
            CP_ASYNC16(Ks + off, (const char*)(kb + (size_t)row * QKVROW) + seg * 16);
            CP_ASYNC16(Vs + off, (const char*)(vb + (size_t)row * QKVROW) + seg * 16);
        }
        CP_COMMIT();
    };

    const int nkt = q0 / 128 + 1;      // 128-key stages
    loadKV(0, 0);

    // Q fragments (after Q + first KV land; drained by the kt=0 wait below)
    uint32_t qf[4][4];
    float o[8][4];
    #pragma unroll
    for (int nt = 0; nt < 8; nt++)
        #pragma unroll
        for (int i = 0; i < 4; i++) o[nt][i] = 0.f;
    float dl[4] = {0.f, 0.f, 0.f, 0.f};

    for (int kt = 0; kt < nkt; kt++) {
        CP_WAIT0();                    // stage kt data complete
        __syncthreads();               // also: all warps done reading buf (kt+1)&1
        if (kt == 0) {
            #pragma unroll
            for (int kh = 0; kh < 4; kh++) {
                uint32_t roff = (uint32_t)(mw + lr + ((lg & 1) << 3)) * APITCH
                              + (uint32_t)(kh*16 + ((lg >> 1) << 3)) * 2u;
                ldmat4(qf[kh], QS + roff);
            }
        }
        if (kt + 1 < nkt) loadKV((kt + 1) & 1, (kt + 1) * 128);

        const uint32_t Ks = ST + (uint32_t)(kt & 1) * ASTG2;
        const uint32_t Vs = Ks + AKV2_B;

        #pragma unroll
        for (int hf = 0; hf < 2; hf++) {   // two 64-key halves
            const int key0 = kt * 128 + hf * 64;
            if (key0 > q0 + mw + 15) break;
            const uint32_t Kh = Ks + (uint32_t)hf * 64u * APITCH;
            const uint32_t Vh = Vs + (uint32_t)hf * 64u * APITCH;

            float sc[8][4];
            #pragma unroll
            for (int nt = 0; nt < 8; nt++)
                #pragma unroll
                for (int i = 0; i < 4; i++) sc[nt][i] = 0.f;

            #pragma unroll
            for (int kh = 0; kh < 4; kh++) {
                #pragma unroll
                for (int bt = 0; bt < 4; bt++) {
                    uint32_t roff = (uint32_t)(bt*16 + lr + ((lg & 2) ? 8 : 0)) * APITCH
                                  + (uint32_t)(kh*16 + ((lg & 1) << 3)) * 2u;
                    uint32_t kf[4];
                    ldmat4(kf, Kh + roff);
                    mma16816h(sc[2*bt+0], qf[kh], kf[0], kf[1]);
                    mma16816h(sc[2*bt+1], qf[kh], kf[2], kf[3]);
                }
            }

            const int row0 = q0 + mw + qr, row1 = row0 + 8;
            if (key0 + 63 > q0 + mw) {
                #pragma unroll
                for (int nt = 0; nt < 8; nt++) {
                    int c0 = key0 + nt*8 + qc;
                    if (c0     > row0) sc[nt][0] = -60000.f;
                    if (c0 + 1 > row0) sc[nt][1] = -60000.f;
                    if (c0     > row1) sc[nt][2] = -60000.f;
                    if (c0 + 1 > row1) sc[nt][3] = -60000.f;
                }
            }

            #pragma unroll
            for (int kh2 = 0; kh2 < 4; kh2++) {
                const int n0t = 2 * kh2, n1t = 2 * kh2 + 1;
                uint32_t pa[4];
                pa[0] = ex2_h2(h2u(__floats2half2_rn(sc[n0t][0], sc[n0t][1])));
                pa[1] = ex2_h2(h2u(__floats2half2_rn(sc[n0t][2], sc[n0t][3])));
                pa[2] = ex2_h2(h2u(__floats2half2_rn(sc[n1t][0], sc[n1t][1])));
                pa[3] = ex2_h2(h2u(__floats2half2_rn(sc[n1t][2], sc[n1t][3])));
                mma16816h(dl, pa, ONESH2, ONESH2);   // dl += P @ 1
                #pragma unroll
                for (int bt = 0; bt < 4; bt++) {
                    uint32_t roff = (uint32_t)(kh2*16 + lr + ((lg & 1) << 3)) * APITCH
                                  + (uint32_t)(bt*16 + ((lg & 2) ? 8 : 0)) * 2u;
                    uint32_t vf[4];
                    ldmat4t(vf, Vh + roff);
                    mma16816h(o[2*bt+0], pa, vf[0], vf[1]);
                    mma16816h(o[2*bt+1], pa, vf[2], vf[3]);
                }
            }
        }
    }

    // ---- normalize + store (dl[0]=row0 sum, dl[2]=row1 sum) ----
    const float inv0 = 1.f / dl[0], inv1 = 1.f / dl[2];
    const int row0 = q0 + mw + qr, row1 = row0 + 8;
    const size_t o0 = (size_t)(b*TSEQ + row0) * DMODEL + h*64;
    const size_t o1 = (size_t)(b*TSEQ + row1) * DMODEL + h*64;
    #pragma unroll
    for (int nt = 0; nt < 8; nt++) {
        int col = nt*8 + qc;
        *reinterpret_cast<__half2*>(ctx + o0 + col) =
            __floats2half2_rn(o[nt][0] * inv0, o[nt][1] * inv0);
        *reinterpret_cast<__half2*>(ctx + o1 + col) =
            __floats2half2_rn(o[nt][2] * inv1, o[nt][3] * inv1);
    }
}

// ---------------- launch ------------------------------------------------------
extern "C" void kernel_launch(void* const* d_in, const int* in_sizes, int n_in,
                              void* d_out, int out_size)
{
    (void)in_sizes; (void)n_in; (void)out_size;
    const float* X     = (const float*)d_in[0];
    const float* Wqkv  = (const float*)d_in[1];
    const float* bqkv  = (const float*)d_in[2];
    const float* Wo    = (const float*)d_in[3];
    const float* bo    = (const float*)d_in[4];
    const float* W1    = (const float*)d_in[5];
    const float* b1    = (const float*)d_in[6];
    const float* W2    = (const float*)d_in[7];
    const float* b2    = (const float*)d_in[8];
    const float* ln1g  = (const float*)d_in[9];
    const float* ln1b  = (const float*)d_in[10];
    const float* ln2g  = (const float*)d_in[11];
    const float* ln2b  = (const float*)d_in[12];
    float* out = (float*)d_out;

    float* x1;
    cudaGetSymbolAddress((void**)&x1, g_x1);

    __half *xn, *xn2, *ctx, *h, *qsp, *wqkvf, *wof, *w1f, *w2f;
    cudaGetSymbolAddress((void**)&xn,    g_xn);
    cudaGetSymbolAddress((void**)&xn2,   g_xn2);
    cudaGetSymbolAddress((void**)&ctx,   g_ctx);
    cudaGetSymbolAddress((void**)&h,     g_h);
    cudaGetSymbolAddress((void**)&qsp,   g_qsp);
    cudaGetSymbolAddress((void**)&wqkvf, g_wqkvf);
    cudaGetSymbolAddress((void**)&wof,   g_wof);
    cudaGetSymbolAddress((void**)&w1f,   g_w1f);
    cudaGetSymbolAddress((void**)&w2f,   g_w2f);

    cudaFuncSetAttribute(gemm_f16<false,false,true,true>,  cudaFuncAttributeMaxDynamicSharedMemorySize, G1SMEM);
    cudaFuncSetAttribute(gemm_f16<false,true,false,false>, cudaFuncAttributeMaxDynamicSharedMemorySize, G1SMEM);
    cudaFuncSetAttribute(gemm_f16<true,false,true,false>,  cudaFuncAttributeMaxDynamicSharedMemorySize, G1SMEM);
    cudaFuncSetAttribute(flash_mma, cudaFuncAttributeMaxDynamicSharedMemorySize, ASMEM);

    // weight transpose + convert to fp16 (one fused launch)
    wconv_all<<<12288, 256>>>(Wqkv, Wo, W1, W2, wqkvf, wof, w1f, w2f);

    // 1. LN1 -> fp16
    ln_f16<<<NTOK, 256>>>(X, ln1g, ln1b, xn);
    // 2. QKV -> fp16, Q cols pre-scaled by log2(e)/8
    gemm_f16<false,false,true,true><<<dim3(QKVROW/128, NTOK/256), 256, G1SMEM>>>(
        xn, wqkvf, bqkv, nullptr, nullptr, qsp, QKVROW, DMODEL);
    // 3. MMA flash attention (max-free log2 softmax, BK=128 stages) -> fp16 ctx
    flash_mma<<<dim3(TSEQ/128, BATCH*NHEADS), 256, ASMEM>>>(qsp, ctx);
    // 4. x1 = ctx @ Wo + bo + X  (fp32 out)
    gemm_f16<false,true,false,false><<<dim3(DMODEL/128, NTOK/256), 256, G1SMEM>>>(
        ctx, wof, bo, X, x1, nullptr, DMODEL, DMODEL);
    // 5. LN2 -> fp16
    ln_f16<<<NTOK, 256>>>(x1, ln2g, ln2b, xn2);
    // 6. h = relu(xn2 @ W1 + b1)  (fp16 out)
    gemm_f16<true,false,true,false><<<dim3(DFF/128, NTOK/256), 256, G1SMEM>>>(
        xn2, w1f, b1, nullptr, nullptr, h, DFF, DMODEL);
    // 7. out = h @ W2 + b2 + x1  (fp32 out)
    gemm_f16<false,true,false,false><<<dim3(DMODEL/128, NTOK/256), 256, G1SMEM>>>(
        h, w2f, b2, x1, out, nullptr, DMODEL, DFF);
}

// round 17
// speedup vs baseline: 1.0193x; 1.0193x over previous
#include <cuda_runtime.h>
#include <cuda_fp16.h>
#include <cstdint>
#include <cstddef>

// Problem constants
#define BATCH   2
#define TSEQ    2048
#define DMODEL  1024
#define NHEADS  16
#define DKEY    64
#define DFF     4096
#define NTOK    (BATCH*TSEQ)          // 4096
#define QKVROW  (3*NHEADS*DKEY)       // 3072

// ---------------- scratch ----------------------------------------------------
__device__ float g_x1  [(size_t)NTOK*DMODEL];

// single fp16 activations
__device__ __half g_xn  [(size_t)NTOK*DMODEL];
__device__ __half g_xn2 [(size_t)NTOK*DMODEL];
__device__ __half g_ctx [(size_t)NTOK*DMODEL];
__device__ __half g_h   [(size_t)NTOK*DFF];

// qkv output: [tok][3072] (Q scaled by log2(e)/8 in cols 0..1023)
__device__ __half g_qsp [(size_t)NTOK*QKVROW];

// single-fp16 transposed weights [N, K] K-major
__device__ __half g_wqkvf[(size_t)QKVROW*DMODEL];
__device__ __half g_wof  [(size_t)DMODEL*DMODEL];
__device__ __half g_w1f  [(size_t)DFF*DMODEL];
__device__ __half g_w2f  [(size_t)DMODEL*DFF];

// ---------------- helpers ----------------------------------------------------
__device__ __forceinline__ uint32_t smem_u32(const void* p) {
    uint32_t a;
    asm("{ .reg .u64 t; cvta.to.shared.u64 t, %1; cvt.u32.u64 %0, t; }"
        : "=r"(a) : "l"(p));
    return a;
}
#define CP_ASYNC16(dst, src) \
    asm volatile("cp.async.cg.shared.global [%0], [%1], 16;" :: "r"(dst), "l"(src) : "memory")
#define CP_COMMIT() asm volatile("cp.async.commit_group;" ::: "memory")
#define CP_WAIT0()  asm volatile("cp.async.wait_group 0;"  ::: "memory")
#define CP_WAIT1()  asm volatile("cp.async.wait_group 1;"  ::: "memory")
#define CP_WAIT2()  asm volatile("cp.async.wait_group 2;"  ::: "memory")

__device__ __forceinline__ void ldmat4(uint32_t (&r)[4], uint32_t addr) {
    asm volatile("ldmatrix.sync.aligned.m8n8.x4.shared.b16 {%0,%1,%2,%3}, [%4];"
        : "=r"(r[0]), "=r"(r[1]), "=r"(r[2]), "=r"(r[3]) : "r"(addr));
}
__device__ __forceinline__ void ldmat4t(uint32_t (&r)[4], uint32_t addr) {
    asm volatile("ldmatrix.sync.aligned.m8n8.x4.trans.shared.b16 {%0,%1,%2,%3}, [%4];"
        : "=r"(r[0]), "=r"(r[1]), "=r"(r[2]), "=r"(r[3]) : "r"(addr));
}
__device__ __forceinline__ void mma16816h(float (&d)[4], const uint32_t (&a)[4],
                                          const uint32_t b0, const uint32_t b1) {
    asm volatile("mma.sync.aligned.m16n8k16.row.col.f32.f16.f16.f32 "
        "{%0,%1,%2,%3}, {%4,%5,%6,%7}, {%8,%9}, {%0,%1,%2,%3};"
        : "+f"(d[0]), "+f"(d[1]), "+f"(d[2]), "+f"(d[3])
        : "r"(a[0]), "r"(a[1]), "r"(a[2]), "r"(a[3]), "r"(b0), "r"(b1));
}
__device__ __forceinline__ uint32_t h2u(__half2 v) {
    union { __half2 h; uint32_t u; } c; c.h = v; return c.u;
}
// packed fp16x2 exp2 on the MUFU pipe (1 issue slot per 2 values)
__device__ __forceinline__ uint32_t ex2_h2(uint32_t x) {
    uint32_t r;
    asm("ex2.approx.f16x2 %0, %1;" : "=r"(r) : "r"(x));
    return r;
}

// ---------------- LayerNorm -> single fp16 -----------------------------------
__inline__ __device__ float warp_sum(float v) {
    #pragma unroll
    for (int o = 16; o > 0; o >>= 1) v += __shfl_xor_sync(0xffffffffu, v, o);
    return v;
}

__global__ __launch_bounds__(256) void ln_f16(
    const float* __restrict__ x, const float* __restrict__ g,
    const float* __restrict__ b, __half* __restrict__ y)
{
    const int row = blockIdx.x;
    const int tid = threadIdx.x;
    const float* xr = x + (size_t)row * DMODEL;

    float4 v = reinterpret_cast<const float4*>(xr)[tid];
    float s  = v.x + v.y + v.z + v.w;
    float sq = v.x*v.x + v.y*v.y + v.z*v.z + v.w*v.w;

    __shared__ float sh_s[8], sh_q[8];
    float ws = warp_sum(s), wq = warp_sum(sq);
    int warp = tid >> 5, lane = tid & 31;
    if (lane == 0) { sh_s[warp] = ws; sh_q[warp] = wq; }
    __syncthreads();
    __shared__ float sh_mean, sh_rstd;
    if (tid == 0) {
        float ts = 0.f, tq = 0.f;
        #pragma unroll
        for (int i = 0; i < 8; i++) { ts += sh_s[i]; tq += sh_q[i]; }
        float mean = ts * (1.0f / DMODEL);
        float var  = tq * (1.0f / DMODEL) - mean * mean;
        sh_mean = mean; sh_rstd = rsqrtf(var + 1e-5f);
    }
    __syncthreads();
    float mean = sh_mean, rstd = sh_rstd;

    float4 gv = reinterpret_cast<const float4*>(g)[tid];
    float4 bv = reinterpret_cast<const float4*>(b)[tid];
    float ox = (v.x - mean) * rstd * gv.x + bv.x;
    float oy = (v.y - mean) * rstd * gv.y + bv.y;
    float oz = (v.z - mean) * rstd * gv.z + bv.z;
    float ow = (v.w - mean) * rstd * gv.w + bv.w;

    size_t o = (size_t)row * DMODEL + tid * 4;
    *reinterpret_cast<__half2*>(y + o)     = __floats2half2_rn(ox, oy);
    *reinterpret_cast<__half2*>(y + o + 2) = __floats2half2_rn(oz, ow);
}

// ---------------- fused weight transpose: all 4 weights in one launch --------
__global__ __launch_bounds__(256) void wconv_all(
    const float* __restrict__ Wqkv, const float* __restrict__ Wo,
    const float* __restrict__ W1,   const float* __restrict__ W2,
    __half* __restrict__ oqkv, __half* __restrict__ oo,
    __half* __restrict__ o1,   __half* __restrict__ o2)
{
    __shared__ float t[32][33];
    const int bid = blockIdx.x;
    const float* W; __half* out; int K, N, n0, k0;
    if (bid < 3072)      { W = Wqkv; out = oqkv; K = 1024; N = 3072;
                           n0 = (bid % 96) * 32;  k0 = (bid / 96) * 32; }
    else if (bid < 4096) { int b2 = bid - 3072; W = Wo; out = oo; K = 1024; N = 1024;
                           n0 = (b2 % 32) * 32;  k0 = (b2 / 32) * 32; }
    else if (bid < 8192) { int b2 = bid - 4096; W = W1; out = o1; K = 1024; N = 4096;
                           n0 = (b2 % 128) * 32; k0 = (b2 / 128) * 32; }
    else                 { int b2 = bid - 8192; W = W2; out = o2; K = 4096; N = 1024;
                           n0 = (b2 % 32) * 32;  k0 = (b2 / 32) * 32; }

    const int tx = threadIdx.x & 31, ty = threadIdx.x >> 5;
    #pragma unroll
    for (int j = 0; j < 4; j++)
        t[ty + j*8][tx] = W[(size_t)(k0 + ty + j*8) * N + n0 + tx];
    __syncthreads();
    #pragma unroll
    for (int j = 0; j < 4; j++) {
        int n = ty + j*8;
        out[(size_t)(n0 + n) * K + k0 + tx] = __float2half_rn(t[tx][n]);
    }
}

// ---------------- 1-product fp16 GEMM, CTA 256x128, warp 64x64, 4-stage ------
#define GPITCH 144u
#define GT_A   (256u * GPITCH)     // 36864
#define GT_B   (128u * GPITCH)     // 18432
#define G1STG  (GT_A + GT_B)       // 55296
#define G1SMEM (4u * G1STG)        // 221184

template<bool RELU, bool RES, bool OF16, bool QKSCALE>
__global__ __launch_bounds__(256, 1) void gemm_f16(
    const __half* __restrict__ Af, const __half* __restrict__ Bf,
    const float* __restrict__ bias, const float* __restrict__ res,
    float* __restrict__ C, __half* __restrict__ Ch, int N, int K)
{
    extern __shared__ char sm[];
    const int tid = threadIdx.x, wid = tid >> 5, lane = tid & 31;
    const int m0 = blockIdx.y * 256, n0 = blockIdx.x * 128;
    const uint32_t sb = smem_u32(sm);

    const int mw = (wid & 3) * 64;
    const int nw = (wid >> 2) * 64;
    const int lg = lane >> 3, lr = lane & 7;

    float d[4][8][4];
    #pragma unroll
    for (int mt = 0; mt < 4; mt++)
        #pragma unroll
        for (int nt = 0; nt < 8; nt++)
            #pragma unroll
            for (int i = 0; i < 4; i++) d[mt][nt][i] = 0.f;

    const int nkt = K >> 6;

    auto loadStage = [&](int s, int k0) {
        const uint32_t st = sb + (uint32_t)s * G1STG;
        const __half* baseA = Af + (size_t)m0 * K + k0;
        const __half* baseB = Bf + (size_t)n0 * K + k0;
        #pragma unroll
        for (int i = 0; i < 8; i++) {
            int lin = i * 256 + tid;
            int row = lin >> 3, seg = lin & 7;
            uint32_t off = (uint32_t)row * GPITCH + (uint32_t)seg * 16u;
            CP_ASYNC16(st + off, (const char*)(baseA + (size_t)row * K + seg * 8));
        }
        #pragma unroll
        for (int i = 0; i < 4; i++) {
            int lin = i * 256 + tid;
            int row = lin >> 3, seg = lin & 7;
            uint32_t off = (uint32_t)row * GPITCH + (uint32_t)seg * 16u;
            CP_ASYNC16(st + GT_A + off, (const char*)(baseB + (size_t)row * K + seg * 8));
        }
        CP_COMMIT();
    };

    auto mmaStage = [&](int s) {
        const uint32_t AS = sb + (uint32_t)s * G1STG;
        const uint32_t BS = AS + GT_A;
        #pragma unroll
        for (int kh = 0; kh < 4; kh++) {
            uint32_t af[4][4];
            #pragma unroll
            for (int mt = 0; mt < 4; mt++) {
                uint32_t roff = (uint32_t)(mw + mt*16 + lr + ((lg & 1) << 3)) * GPITCH
                              + (uint32_t)(kh*16 + ((lg >> 1) << 3)) * 2u;
                ldmat4(af[mt], AS + roff);
            }
            #pragma unroll
            for (int bt = 0; bt < 4; bt++) {
                uint32_t roff = (uint32_t)(nw + bt*16 + lr + ((lg & 2) ? 8 : 0)) * GPITCH
                              + (uint32_t)(kh*16 + ((lg & 1) << 3)) * 2u;
                uint32_t bh[4];
                ldmat4(bh, BS + roff);
                #pragma unroll
                for (int mt = 0; mt < 4; mt++) {
                    mma16816h(d[mt][2*bt+0], af[mt], bh[0], bh[1]);
                    mma16816h(d[mt][2*bt+1], af[mt], bh[2], bh[3]);
                }
            }
        }
    };

    loadStage(0, 0);
    loadStage(1, 64);
    loadStage(2, 128);
    for (int kt = 0; kt < nkt; kt++) {
        if (kt + 2 < nkt)      { CP_WAIT2(); }
        else if (kt + 1 < nkt) { CP_WAIT1(); }
        else                   { CP_WAIT0(); }
        __syncthreads();
        if (kt + 3 < nkt) loadStage((kt + 3) & 3, (kt + 3) << 6);
        mmaStage(kt & 3);
    }

    const int qr = lane >> 2;
    const int qc = (lane & 3) * 2;
    #pragma unroll
    for (int mt = 0; mt < 4; mt++) {
        const int r0 = m0 + mw + mt * 16 + qr;
        const int r1 = r0 + 8;
        #pragma unroll
        for (int nt = 0; nt < 8; nt++) {
            const int c = n0 + nw + nt * 8 + qc;
            float2 bb = *reinterpret_cast<const float2*>(bias + c);
            float2 o0, o1;
            o0.x = d[mt][nt][0] + bb.x; o0.y = d[mt][nt][1] + bb.y;
            o1.x = d[mt][nt][2] + bb.x; o1.y = d[mt][nt][3] + bb.y;
            if (QKSCALE) {
                // Q columns: 1/8 (dk scale) x log2(e)  -> scores in log2 domain
                const float sc = (c < 1024) ? 0.18033688011112042f : 1.0f;
                o0.x *= sc; o0.y *= sc; o1.x *= sc; o1.y *= sc;
            }
            if (RELU) {
                o0.x = fmaxf(o0.x, 0.f); o0.y = fmaxf(o0.y, 0.f);
                o1.x = fmaxf(o1.x, 0.f); o1.y = fmaxf(o1.y, 0.f);
            }
            if (RES) {
                float2 u0 = *reinterpret_cast<const float2*>(res + (size_t)r0 * N + c);
                float2 u1 = *reinterpret_cast<const float2*>(res + (size_t)r1 * N + c);
                o0.x += u0.x; o0.y += u0.y; o1.x += u1.x; o1.y += u1.y;
            }
            if (OF16) {
                *reinterpret_cast<__half2*>(Ch + (size_t)r0 * N + c) = __floats2half2_rn(o0.x, o0.y);
                *reinterpret_cast<__half2*>(Ch + (size_t)r1 * N + c) = __floats2half2_rn(o1.x, o1.y);
            } else {
                *reinterpret_cast<float2*>(C + (size_t)r0 * N + c) = o0;
                *reinterpret_cast<float2*>(C + (size_t)r1 * N + c) = o1;
            }
        }
    }
}

// ---------------- MMA flash attention: BQ=64, 4 warps, 4 CTAs/SM -------------
// Max-free log2-domain softmax; row sums via ones-MMA on the tensor pipe.
// 2-stage BK=64 ring, single wait+sync per tile (load issued after sync).
#define APITCH 144u
#define AQ_B   (64u * APITCH)              // 9216
#define AKV_B  (64u * APITCH)              // 9216 per K or V tile
#define ASTG_B (2u * AKV_B)                // K+V stage = 18432
#define ASMEM  (AQ_B + 2u * ASTG_B)        // 46080  (4 CTAs/SM: 180KB)
#define ONESH2 0x3C003C00u                 // half2(1,1)

__global__ __launch_bounds__(128, 4) void flash_mma(
    const __half* __restrict__ qsp, __half* __restrict__ ctx)
{
    extern __shared__ char sm[];
    const int tid = threadIdx.x, wid = tid >> 5, lane = tid & 31;
    const int q0 = (31 - blockIdx.x) * 64;     // heavy blocks first
    const int bh = blockIdx.y, b = bh >> 4, h = bh & 15;
    const int mw = wid * 16;
    const int lg = lane >> 3, lr = lane & 7;
    const int qr = lane >> 2, qc = (lane & 3) * 2;

    const uint32_t sb = smem_u32(sm);
    const uint32_t QS = sb;
    const uint32_t ST = sb + AQ_B;

    {
        const __half* qb = qsp + (size_t)(b*TSEQ + q0) * QKVROW + h*64;
        #pragma unroll
        for (int i = 0; i < 4; i++) {
            int lin = i * 128 + tid;
            int row = lin >> 3, seg = lin & 7;
            uint32_t off = (uint32_t)row * APITCH + (uint32_t)seg * 16u;
            CP_ASYNC16(QS + off, (const char*)(qb + (size_t)row * QKVROW) + seg * 16);
        }
        CP_COMMIT();
    }

    auto loadKV = [&](int s, int key0) {
        const uint32_t Ks = ST + (uint32_t)s * ASTG_B;
        const uint32_t Vs = Ks + AKV_B;
        const __half* kb = qsp + (size_t)(b*TSEQ + key0) * QKVROW + 1024 + h*64;
        const __half* vb = qsp + (size_t)(b*TSEQ + key0) * QKVROW + 2048 + h*64;
        #pragma unroll
        for (int i = 0; i < 4; i++) {
            int lin = i * 128 + tid;
            int row = lin >> 3, seg = lin & 7;
            uint32_t off = (uint32_t)row * APITCH + (uint32_t)seg * 16u;
            CP_ASYNC16(Ks + off, (const char*)(kb + (size_t)row * QKVROW) + seg * 16);
            CP_ASYNC16(Vs + off, (const char*)(vb + (size_t)row * QKVROW) + seg * 16);
        }
        CP_COMMIT();
    };

    const int nkt = q0 / 64 + 1;
    loadKV(0, 0);

    uint32_t qf[4][4];
    float o[8][4];
    #pragma unroll
    for (int nt = 0; nt < 8; nt++)
        #pragma unroll
        for (int i = 0; i < 4; i++) o[nt][i] = 0.f;
    float dl[4] = {0.f, 0.f, 0.f, 0.f};

    for (int kt = 0; kt < nkt; kt++) {
        const int key0 = kt * 64;
        CP_WAIT0();                    // Q (kt=0) + stage kt complete
        __syncthreads();               // all warps done reading buf (kt+1)&1
        if (kt == 0) {
            #pragma unroll
            for (int kh = 0; kh < 4; kh++) {
                uint32_t roff = (uint32_t)(mw + lr + ((lg & 1) << 3)) * APITCH
                              + (uint32_t)(kh*16 + ((lg >> 1) << 3)) * 2u;
                ldmat4(qf[kh], QS + roff);
            }
        }
        if (kt + 1 < nkt) loadKV((kt + 1) & 1, key0 + 64);

        if (key0 <= q0 + mw + 15) {
            const uint32_t Ks = ST + (uint32_t)(kt & 1) * ASTG_B;
            const uint32_t Vs = Ks + AKV_B;

            float sc[8][4];
            #pragma unroll
            for (int nt = 0; nt < 8; nt++)
                #pragma unroll
                for (int i = 0; i < 4; i++) sc[nt][i] = 0.f;

            #pragma unroll
            for (int kh = 0; kh < 4; kh++) {
                #pragma unroll
                for (int bt = 0; bt < 4; bt++) {
                    uint32_t roff = (uint32_t)(bt*16 + lr + ((lg & 2) ? 8 : 0)) * APITCH
                                  + (uint32_t)(kh*16 + ((lg & 1) << 3)) * 2u;
                    uint32_t kf[4];
                    ldmat4(kf, Ks + roff);
                    mma16816h(sc[2*bt+0], qf[kh], kf[0], kf[1]);
                    mma16816h(sc[2*bt+1], qf[kh], kf[2], kf[3]);
                }
            }

            const int row0 = q0 + mw + qr, row1 = row0 + 8;
            if (key0 + 63 > q0 + mw) {
                #pragma unroll
                for (int nt = 0; nt < 8; nt++) {
                    int c0 = key0 + nt*8 + qc;
                    if (c0     > row0) sc[nt][0] = -60000.f;
                    if (c0 + 1 > row0) sc[nt][1] = -60000.f;
                    if (c0     > row1) sc[nt][2] = -60000.f;
                    if (c0 + 1 > row1) sc[nt][3] = -60000.f;
                }
            }

            #pragma unroll
            for (int kh2 = 0; kh2 < 4; kh2++) {
                const int n0t = 2 * kh2, n1t = 2 * kh2 + 1;
                uint32_t pa[4];
                pa[0] = ex2_h2(h2u(__floats2half2_rn(sc[n0t][0], sc[n0t][1])));
                pa[1] = ex2_h2(h2u(__floats2half2_rn(sc[n0t][2], sc[n0t][3])));
                pa[2] = ex2_h2(h2u(__floats2half2_rn(sc[n1t][0], sc[n1t][1])));
                pa[3] = ex2_h2(h2u(__floats2half2_rn(sc[n1t][2], sc[n1t][3])));
                mma16816h(dl, pa, ONESH2, ONESH2);   // dl += P @ 1
                #pragma unroll
                for (int bt = 0; bt < 4; bt++) {
                    uint32_t roff = (uint32_t)(kh2*16 + lr + ((lg & 1) << 3)) * APITCH
                                  + (uint32_t)(bt*16 + ((lg & 2) ? 8 : 0)) * 2u;
                    uint32_t vf[4];
                    ldmat4t(vf, Vs + roff);
                    mma16816h(o[2*bt+0], pa, vf[0], vf[1]);
                    mma16816h(o[2*bt+1], pa, vf[2], vf[3]);
                }
            }
        }
    }

    // ---- normalize + store (dl[0]=row0 sum, dl[2]=row1 sum) ----
    const float inv0 = 1.f / dl[0], inv1 = 1.f / dl[2];
    const int row0 = q0 + mw + qr, row1 = row0 + 8;
    const size_t o0 = (size_t)(b*TSEQ + row0) * DMODEL + h*64;
    const size_t o1 = (size_t)(b*TSEQ + row1) * DMODEL + h*64;
    #pragma unroll
    for (int nt = 0; nt < 8; nt++) {
        int col = nt*8 + qc;
        *reinterpret_cast<__half2*>(ctx + o0 + col) =
            __floats2half2_rn(o[nt][0] * inv0, o[nt][1] * inv0);
        *reinterpret_cast<__half2*>(ctx + o1 + col) =
            __floats2half2_rn(o[nt][2] * inv1, o[nt][3] * inv1);
    }
}

// ---------------- launch ------------------------------------------------------
extern "C" void kernel_launch(void* const* d_in, const int* in_sizes, int n_in,
                              void* d_out, int out_size)
{
    (void)in_sizes; (void)n_in; (void)out_size;
    const float* X     = (const float*)d_in[0];
    const float* Wqkv  = (const float*)d_in[1];
    const float* bqkv  = (const float*)d_in[2];
    const float* Wo    = (const float*)d_in[3];
    const float* bo    = (const float*)d_in[4];
    const float* W1    = (const float*)d_in[5];
    const float* b1    = (const float*)d_in[6];
    const float* W2    = (const float*)d_in[7];
    const float* b2    = (const float*)d_in[8];
    const float* ln1g  = (const float*)d_in[9];
    const float* ln1b  = (const float*)d_in[10];
    const float* ln2g  = (const float*)d_in[11];
    const float* ln2b  = (const float*)d_in[12];
    float* out = (float*)d_out;

    float* x1;
    cudaGetSymbolAddress((void**)&x1, g_x1);

    __half *xn, *xn2, *ctx, *h, *qsp, *wqkvf, *wof, *w1f, *w2f;
    cudaGetSymbolAddress((void**)&xn,    g_xn);
    cudaGetSymbolAddress((void**)&xn2,   g_xn2);
    cudaGetSymbolAddress((void**)&ctx,   g_ctx);
    cudaGetSymbolAddress((void**)&h,     g_h);
    cudaGetSymbolAddress((void**)&qsp,   g_qsp);
    cudaGetSymbolAddress((void**)&wqkvf, g_wqkvf);
    cudaGetSymbolAddress((void**)&wof,   g_wof);
    cudaGetSymbolAddress((void**)&w1f,   g_w1f);
    cudaGetSymbolAddress((void**)&w2f,   g_w2f);

    cudaFuncSetAttribute(gemm_f16<false,false,true,true>,  cudaFuncAttributeMaxDynamicSharedMemorySize, G1SMEM);
    cudaFuncSetAttribute(gemm_f16<false,true,false,false>, cudaFuncAttributeMaxDynamicSharedMemorySize, G1SMEM);
    cudaFuncSetAttribute(gemm_f16<true,false,true,false>,  cudaFuncAttributeMaxDynamicSharedMemorySize, G1SMEM);
    cudaFuncSetAttribute(flash_mma, cudaFuncAttributeMaxDynamicSharedMemorySize, ASMEM);

    // weight transpose + convert to fp16 (one fused launch)
    wconv_all<<<12288, 256>>>(Wqkv, Wo, W1, W2, wqkvf, wof, w1f, w2f);

    // 1. LN1 -> fp16
    ln_f16<<<NTOK, 256>>>(X, ln1g, ln1b, xn);
    // 2. QKV -> fp16, Q cols pre-scaled by log2(e)/8
    gemm_f16<false,false,true,true><<<dim3(QKVROW/128, NTOK/256), 256, G1SMEM>>>(
        xn, wqkvf, bqkv, nullptr, nullptr, qsp, QKVROW, DMODEL);
    // 3. MMA flash attention (BQ=64, 4 CTAs/SM) -> fp16 ctx
    flash_mma<<<dim3(TSEQ/64, BATCH*NHEADS), 128, ASMEM>>>(qsp, ctx);
    // 4. x1 = ctx @ Wo + bo + X  (fp32 out)
    gemm_f16<false,true,false,false><<<dim3(DMODEL/128, NTOK/256), 256, G1SMEM>>>(
        ctx, wof, bo, X, x1, nullptr, DMODEL, DMODEL);
    // 5. LN2 -> fp16
    ln_f16<<<NTOK, 256>>>(x1, ln2g, ln2b, xn2);
    // 6. h = relu(xn2 @ W1 + b1)  (fp16 out)
    gemm_f16<true,false,true,false><<<dim3(DFF/128, NTOK/256), 256, G1SMEM>>>(
        xn2, w1f, b1, nullptr, nullptr, h, DFF, DMODEL);
    // 7. out = h @ W2 + b2 + x1  (fp32 out)
    gemm_f16<false,true,false,false><<<dim3(DMODEL/128, NTOK/256), 256, G1SMEM>>>(
        h, w2f, b2, x1, out, nullptr, DMODEL, DFF);
}